// round 12
// baseline (speedup 1.0000x reference)
#include <cuda_runtime.h>

#define TT 4096
#define BB 32
#define DD 128
#define D3 384
#define NSTAGE 16
#define NSCAN 64   // 2 CTAs (one cluster) per batch element

// Scratch for xi = x @ Wi + bi : [T, B, 3D] fp32 = 201 MB.
__device__ float g_xi[(size_t)TT * BB * D3];
__device__ int g_reset_mode;  // 0 = int32, 1 = float32, 2 = uint8/bool
__device__ int g_ready[TT];   // per-timestep xi completion flags

// ---------------------------------------------------------------------------
// Helpers
// ---------------------------------------------------------------------------
__device__ __forceinline__ int read_reset(const void* r, int idx, int mode) {
    if (mode == 0) return ((const int*)r)[idx] != 0;
    if (mode == 1) return ((const float*)r)[idx] != 0.0f;
    return ((const unsigned char*)r)[idx] != 0;
}

__device__ __forceinline__ unsigned long long pack2(float lo, float hi) {
    unsigned long long p;
    asm("mov.b64 %0, {%1, %2};" : "=l"(p) : "f"(lo), "f"(hi));
    return p;
}

__device__ __forceinline__ void fma2(unsigned long long& acc,
                                     unsigned long long a,
                                     unsigned long long b) {
    asm("fma.rn.f32x2 %0, %1, %2, %0;" : "+l"(acc) : "l"(a), "l"(b));
}

__device__ __forceinline__ unsigned long long add2(unsigned long long a,
                                                   unsigned long long b) {
    unsigned long long r;
    asm("add.rn.f32x2 %0, %1, %2;" : "=l"(r) : "l"(a), "l"(b));
    return r;
}

__device__ __forceinline__ float hsum2(unsigned long long a) {
    float lo, hi;
    asm("mov.b64 {%0, %1}, %2;" : "=f"(lo), "=f"(hi) : "l"(a));
    return lo + hi;
}

__device__ __forceinline__ void cp_async16(void* smem_dst, const void* gmem_src) {
    unsigned s = (unsigned)__cvta_generic_to_shared(smem_dst);
    asm volatile("cp.async.cg.shared.global [%0], [%1], 16;"
                 :: "r"(s), "l"(gmem_src) : "memory");
}

__device__ __forceinline__ int ld_acq(const int* p) {
    int v;
    asm volatile("ld.acquire.gpu.b32 %0, [%1];" : "=r"(v) : "l"(p) : "memory");
    return v;
}

__device__ __forceinline__ void st_rel(int* p, int v) {
    asm volatile("st.release.gpu.b32 [%0], %1;" :: "l"(p), "r"(v) : "memory");
}

__device__ __forceinline__ unsigned smem_u32(const void* p) {
    return (unsigned)__cvta_generic_to_shared(p);
}

__device__ __forceinline__ int ld_acq_cta_smem(const int* p) {
    int v;
    asm volatile("ld.acquire.cta.shared.b32 %0, [%1];"
                 : "=r"(v) : "r"(smem_u32(p)) : "memory");
    return v;
}

__device__ __forceinline__ void st_rel_cta_smem(int* p, int v) {
    asm volatile("st.release.cta.shared.b32 [%0], %1;"
                 :: "r"(smem_u32(p)), "r"(v) : "memory");
}

__device__ __forceinline__ unsigned mapa_peer(unsigned addr, unsigned rank) {
    unsigned r;
    asm("mapa.shared::cluster.u32 %0, %1, %2;" : "=r"(r) : "r"(addr), "r"(rank));
    return r;
}

__device__ __forceinline__ void dsmem_st_f32(unsigned addr, float v) {
    asm volatile("st.shared::cluster.f32 [%0], %1;" :: "r"(addr), "f"(v) : "memory");
}

__device__ __forceinline__ void mbar_arrive_cluster(unsigned addr) {
    asm volatile("mbarrier.arrive.release.cluster.shared::cluster.b64 _, [%0];"
                 :: "r"(addr) : "memory");
}

__device__ __forceinline__ void mbar_wait_cluster(unsigned addr, int parity) {
    unsigned done;
    asm volatile(
        "{\n\t.reg .pred p;\n\t"
        "mbarrier.try_wait.parity.acquire.cluster.shared::cta.b64 p, [%1], %2;\n\t"
        "selp.b32 %0, 1, 0, p;\n\t}"
        : "=r"(done) : "r"(addr), "r"((unsigned)parity) : "memory");
    if (!done) {
        asm volatile(
            "{\n\t.reg .pred P1;\n\t"
            "W_%=:\n\t"
            "mbarrier.try_wait.parity.acquire.cluster.shared::cta.b64 P1, [%0], %1;\n\t"
            "@P1 bra.uni D_%=;\n\t"
            "bra.uni W_%=;\n\t"
            "D_%=:\n\t}"
            :: "r"(addr), "r"((unsigned)parity) : "memory");
    }
}

// ---------------------------------------------------------------------------
// Probe resets dtype + clear ready flags for this replay.
// ---------------------------------------------------------------------------
__global__ void probe_clear_kernel(const unsigned int* __restrict__ r) {
    for (int i = threadIdx.x; i < TT; i += blockDim.x) g_ready[i] = 0;
    __shared__ int s_not01, s_notf;
    if (threadIdx.x == 0) { s_not01 = 0; s_notf = 0; }
    __syncthreads();
    int not01 = 0, notf = 0;
    for (int i = threadIdx.x; i < 32768; i += blockDim.x) {
        unsigned v = r[i];
        if (v != 0u && v != 1u) not01 = 1;
        if (v != 0u && v != 0x3F800000u) notf = 1;
    }
    if (not01) atomicOr(&s_not01, 1);
    if (notf)  atomicOr(&s_notf, 1);
    __syncthreads();
    if (threadIdx.x == 0)
        g_reset_mode = (!s_not01) ? 0 : ((!s_notf) ? 1 : 2);
}

// ---------------------------------------------------------------------------
// GEMM role: blocks NSCAN..grid-1. Block gb owns timesteps t = gb + k*ngemm.
// ---------------------------------------------------------------------------
__device__ __forceinline__ void gemm_role(const float* __restrict__ x,
                                          const float* __restrict__ Wi,
                                          const float* __restrict__ bi,
                                          int gb, int ngemm) {
    __shared__ __align__(16) float xs[2][DD];
    const int j = threadIdx.x;

    unsigned long long w2[64];
#pragma unroll
    for (int k = 0; k < 64; k++)
        w2[k] = pack2(Wi[(2 * k) * D3 + j], Wi[(2 * k + 1) * D3 + j]);
    const float bj = bi[j];

    for (int t = gb; t < TT; t += ngemm) {
        const int r0 = t * BB;
        for (int rp = 0; rp < BB; rp += 2) {
            const int r = r0 + rp;
            if (j < 256)
                xs[j >> 7][j & 127] = x[(size_t)(r + (j >> 7)) * DD + (j & 127)];
            __syncthreads();

            unsigned long long a00 = 0ull, a01 = 0ull, a10 = 0ull, a11 = 0ull;
            const ulonglong2* x0 = (const ulonglong2*)xs[0];
            const ulonglong2* x1 = (const ulonglong2*)xs[1];
#pragma unroll
            for (int k = 0; k < 32; k++) {
                ulonglong2 v0 = x0[k];
                ulonglong2 v1 = x1[k];
                fma2(a00, w2[2 * k],     v0.x);
                fma2(a01, w2[2 * k + 1], v0.y);
                fma2(a10, w2[2 * k],     v1.x);
                fma2(a11, w2[2 * k + 1], v1.y);
            }
            g_xi[(size_t)r * D3 + j]       = bj + hsum2(add2(a00, a01));
            g_xi[(size_t)(r + 1) * D3 + j] = bj + hsum2(add2(a10, a11));
            __syncthreads();
        }
        __threadfence();
        __syncthreads();
        if (j == 0) st_rel(&g_ready[t], 1);
    }
}

// ---------------------------------------------------------------------------
// Scan role: one cluster (2 CTAs) per batch element. CTA `half` owns the 192
// Wh columns {g*128 + 64*half + [0,64)} and the gate outputs d in
// [64*half, 64*half+64).
// Threads:  0..191  dot (full-k, one column each; two k-phases)
//         192..255  gate (preload xi during dot; gate math in window;
//                   DSMEM-push new h to peer + arrive on peer mbar[(t+1)&1])
//         256..271  ys store (STG.128 of row t-1)
//         272       listener (at step t>0: waits mbar[t&1] for the peer's
//                   h(t-1) pushes made in the peer's window of step t-1 —
//                   data already in flight, so no circular wait — then
//                   publishes CTA-local token rflag = t)
//         288..383  xi refill (cp.async ring, exclusive group state)
// Per step: dotA(local k-half) -> [spin rflag>=t] -> dotB(remote k-half)
//           -> B1 -> gate/ys/refill window -> B2.
// ---------------------------------------------------------------------------
__device__ __forceinline__ void scan_role(const void* __restrict__ resets,
                                          const float* __restrict__ Wh,
                                          const float* __restrict__ bhn,
                                          float* __restrict__ ys,
                                          int b, int half) {
    __shared__ __align__(16) float h[2][DD];
    __shared__ float hh[192];
    __shared__ __align__(16) float xstage[NSTAGE][D3];
    __shared__ unsigned char srst[TT];
    __shared__ __align__(8) unsigned long long mbar[2];
    __shared__ int rflag;

    const int j = threadIdx.x;
    const int mode = g_reset_mode;

    const bool is_dot  = (j < 192);
    const bool is_gate = (j >= 192 && j < 256);
    const bool is_ys   = (j >= 256 && j < 272);
    const bool is_lsn  = (j == 272);
    const bool is_refl = (j >= 288);
    const int  rl      = j - 288;          // refill lane 0..95
    const int  gg      = j - 192;          // gate lane 0..63
    const int  d       = 64 * half + gg;   // gate output index

    // Dot thread column + full-k weights (others leave w2 untouched).
    unsigned long long w2[64];
    if (is_dot) {
        const int col = 128 * (j >> 6) + 64 * half + (j & 63);
#pragma unroll
        for (int k = 0; k < 64; k++)
            w2[k] = pack2(Wh[(2 * k) * D3 + col], Wh[(2 * k + 1) * D3 + col]);
    }
    const float bn = is_gate ? bhn[d] : 0.0f;

    if (j < DD) { h[0][j] = 0.0f; h[1][j] = 0.0f; }
    if (j == 0) {
        rflag = 0;
        asm volatile("mbarrier.init.shared.b64 [%0], 64;" :: "r"(smem_u32(&mbar[0])) : "memory");
        asm volatile("mbarrier.init.shared.b64 [%0], 64;" :: "r"(smem_u32(&mbar[1])) : "memory");
        asm volatile("fence.mbarrier_init.release.cluster;" ::: "memory");
    }
    for (int t = j; t < TT; t += 384)
        srst[t] = (unsigned char)read_reset(resets, t * BB + b, mode);
    __syncthreads();
    // Both CTAs' mbarriers must be live before any cross-CTA arrive.
    asm volatile("barrier.cluster.arrive.aligned;" ::: "memory");
    asm volatile("barrier.cluster.wait.aligned;" ::: "memory");

    const unsigned peer = (unsigned)(half ^ 1);
    const unsigned peer_h0   = mapa_peer(smem_u32(&h[0][0]), peer);
    const unsigned peer_h1   = mapa_peer(smem_u32(&h[1][0]), peer);
    const unsigned peer_mbar = mapa_peer(smem_u32(&mbar[0]), peer);
    const unsigned my_mbar   = smem_u32(&mbar[0]);

    // Prime the xi ring (refill threads own all cp.async group state).
    if (is_refl) {
        for (int s = 0; s < NSTAGE; s++) {
            while (ld_acq(&g_ready[s]) == 0) __nanosleep(64);
            cp_async16(&xstage[s][rl * 4],
                       g_xi + ((size_t)s * BB + b) * D3 + rl * 4);
            asm volatile("cp.async.commit_group;" ::: "memory");
        }
        asm volatile("cp.async.wait_group %0;" :: "n"(NSTAGE - 1) : "memory");
    }
    __syncthreads();

    float* yp = is_ys ? (ys + (size_t)b * DD + 64 * half + (j - 256) * 4) : ys;
    const float* rp = g_xi + ((size_t)NSTAGE * BB + b) * D3 + rl * 4;

    const int lbase = 32 * half;           // local  k-half in w2 pair index
    const int rbase = 32 * (1 - half);     // remote k-half
    int F = NSTAGE;
    int ph0 = 0, ph1 = 0;
    int p = 0;
    for (int t = 0; t < TT; t++) {
        const int st = t & (NSTAGE - 1);

        // ---------- dot phase ----------
        float xr = 0.0f, xz = 0.0f, xn = 0.0f;
        int rst = 0;
        unsigned long long a0 = 0ull, a1 = 0ull, a2 = 0ull, a3 = 0ull;

        if (is_dot) {
            // phase A: CTA-local k-half of h(t-1) (our gate wrote it; B2-covered)
            const ulonglong2* hl = (const ulonglong2*)&h[p][64 * half];
#pragma unroll
            for (int i = 0; i < 8; i++) {
                ulonglong2 va = hl[2 * i];
                ulonglong2 vb = hl[2 * i + 1];
                fma2(a0, w2[lbase + 4 * i + 0], va.x);
                fma2(a1, w2[lbase + 4 * i + 1], va.y);
                fma2(a2, w2[lbase + 4 * i + 2], vb.x);
                fma2(a3, w2[lbase + 4 * i + 3], vb.y);
            }
            // wait for the peer half of h(t-1) (token published by listener)
            if (ld_acq_cta_smem(&rflag) < t) {
                while (ld_acq_cta_smem(&rflag) < t) __nanosleep(32);
            }
            const ulonglong2* hr = (const ulonglong2*)&h[p][64 * (1 - half)];
#pragma unroll
            for (int i = 0; i < 8; i++) {
                ulonglong2 va = hr[2 * i];
                ulonglong2 vb = hr[2 * i + 1];
                fma2(a0, w2[rbase + 4 * i + 0], va.x);
                fma2(a1, w2[rbase + 4 * i + 1], va.y);
                fma2(a2, w2[rbase + 4 * i + 2], vb.x);
                fma2(a3, w2[rbase + 4 * i + 3], vb.y);
            }
            hh[j] = hsum2(add2(add2(a0, a1), add2(a2, a3)));
        } else if (is_gate) {
            // preload xi + reset so refill may overwrite slot st in the window
            const float* xi_s = xstage[st];
            xr = xi_s[d];
            xz = xi_s[128 + d];
            xn = xi_s[256 + d];
            rst = srst[t];
        } else if (is_lsn && t > 0) {
            // Wait for the peer's h(t-1) pushes (made in peer window t-1 —
            // already in flight; never blocks on the peer's CURRENT step).
            const int idx = t & 1;
            const int par = idx ? ph1 : ph0;
            mbar_wait_cluster(my_mbar + idx * 8, par);
            if (idx) ph1 ^= 1; else ph0 ^= 1;
            st_rel_cta_smem(&rflag, t);
        }
        __syncthreads();  // B1: hh published; slot-st reads done.

        // ---------- window ----------
        if (is_gate) {
            float hr = rst ? 0.0f : hh[gg];
            float hz = rst ? 0.0f : hh[64 + gg];
            float hn = rst ? 0.0f : hh[128 + gg];
            float sn = hn + bn;
            float rg = __fdividef(1.0f, 1.0f + __expf(-(xr + hr)));
            float zg = __fdividef(1.0f, 1.0f + __expf(-(xz + hz)));
            float ar = xn + rg * sn;
            float ng = __fdividef(2.0f, 1.0f + __expf(-2.0f * ar)) - 1.0f;
            float hp = rst ? 0.0f : h[p][d];
            float nh = (1.0f - zg) * ng + zg * hp;
            h[p ^ 1][d] = nh;
            // push h(t)[d] to peer; arrive on the barrier its listener will
            // wait on at step t+1 (idx = (t+1)&1).
            unsigned pha = ((p ^ 1) ? peer_h1 : peer_h0) + d * 4;
            dsmem_st_f32(pha, nh);
            mbar_arrive_cluster(peer_mbar + ((t + 1) & 1) * 8);
        } else if (is_ys) {
            if (t > 0) {                 // h[p] holds step t-1's output
                float4 v = *(const float4*)&h[p][64 * half + (j - 256) * 4];
                *(float4*)yp = v;
                yp += BB * DD;
            }
        } else if (is_refl) {
            const int need = t + NSTAGE;
            if (need < TT) {
                if (need >= F) {
                    int probe_t = need + 256;
                    if (probe_t > TT - 1) probe_t = TT - 1;
                    if (ld_acq(&g_ready[probe_t])) {
                        F = probe_t + 1;
                    } else {
                        while (ld_acq(&g_ready[need]) == 0) __nanosleep(64);
                        F = need + 1;
                    }
                }
                cp_async16(&xstage[st][rl * 4], rp);
            }
            rp += (size_t)BB * D3;
            asm volatile("cp.async.commit_group;" ::: "memory");
            asm volatile("cp.async.wait_group %0;" :: "n"(NSTAGE - 1) : "memory");
        }
        __syncthreads();  // B2: local h half + next xi slot published.

        p ^= 1;
    }

    if (is_ys) {                          // row TT-1
        float4 v = *(const float4*)&h[p][64 * half + (j - 256) * 4];
        *(float4*)yp = v;
    }

    // Peer may still be DSMEM-writing into this CTA's smem — don't exit early.
    asm volatile("barrier.cluster.arrive.aligned;" ::: "memory");
    asm volatile("barrier.cluster.wait.aligned;" ::: "memory");
}

// ---------------------------------------------------------------------------
// Fused kernel, cluster (2,1,1). Blocks 0..63: scan pairs (b = blk/2,
// half = blk&1 == cluster rank). Blocks 64..: GEMM (those clusters never use
// DSMEM/cluster barriers). High reg count -> 1 CTA/SM; grid == #SMs (even)
// => every CTA resident in wave 1, so the handshakes cannot deadlock.
// ---------------------------------------------------------------------------
__global__ void __cluster_dims__(2, 1, 1) __launch_bounds__(384, 1)
fused_kernel(const float* __restrict__ x,
             const void* __restrict__ resets,
             const float* __restrict__ Wi,
             const float* __restrict__ bi,
             const float* __restrict__ Wh,
             const float* __restrict__ bhn,
             float* __restrict__ ys,
             int ngemm) {
    if (blockIdx.x < NSCAN)
        scan_role(resets, Wh, bhn, ys, blockIdx.x >> 1, blockIdx.x & 1);
    else
        gemm_role(x, Wi, bi, (int)blockIdx.x - NSCAN, ngemm);
}

// ---------------------------------------------------------------------------
extern "C" void kernel_launch(void* const* d_in, const int* in_sizes, int n_in,
                              void* d_out, int out_size) {
    const float* x      = (const float*)d_in[0];
    const void*  resets = d_in[1];
    const float* Wi     = (const float*)d_in[2];
    const float* bi     = (const float*)d_in[3];
    const float* Wh     = (const float*)d_in[4];
    const float* bhn    = (const float*)d_in[5];
    float* ys = (float*)d_out;

    int dev = 0, nsm = 148;
    cudaGetDevice(&dev);
    cudaDeviceGetAttribute(&nsm, cudaDevAttrMultiProcessorCount, dev);
    nsm &= ~1;                       // cluster size 2 divides the grid
    if (nsm < NSCAN + 2) nsm = NSCAN + 2;

    probe_clear_kernel<<<1, 256>>>((const unsigned int*)resets);
    fused_kernel<<<nsm, 384>>>(x, resets, Wi, bi, Wh, bhn, ys, nsm - NSCAN);
}

// round 13
// speedup vs baseline: 2.4555x; 2.4555x over previous
#include <cuda_runtime.h>

#define TT 4096
#define BB 32
#define DD 128
#define D3 384
#define NSTAGE 16

// Scratch for xi = x @ Wi + bi : [T, B, 3D] fp32 = 201 MB.
__device__ float g_xi[(size_t)TT * BB * D3];
__device__ int g_reset_mode;  // 0 = int32, 1 = float32, 2 = uint8/bool
__device__ int g_ready[TT];   // per-timestep xi completion flags

// ---------------------------------------------------------------------------
// Helpers
// ---------------------------------------------------------------------------
__device__ __forceinline__ int read_reset(const void* r, int idx, int mode) {
    if (mode == 0) return ((const int*)r)[idx] != 0;
    if (mode == 1) return ((const float*)r)[idx] != 0.0f;
    return ((const unsigned char*)r)[idx] != 0;
}

__device__ __forceinline__ unsigned long long pack2(float lo, float hi) {
    unsigned long long p;
    asm("mov.b64 %0, {%1, %2};" : "=l"(p) : "f"(lo), "f"(hi));
    return p;
}

__device__ __forceinline__ void fma2(unsigned long long& acc,
                                     unsigned long long a,
                                     unsigned long long b) {
    asm("fma.rn.f32x2 %0, %1, %2, %0;" : "+l"(acc) : "l"(a), "l"(b));
}

__device__ __forceinline__ unsigned long long add2(unsigned long long a,
                                                   unsigned long long b) {
    unsigned long long r;
    asm("add.rn.f32x2 %0, %1, %2;" : "=l"(r) : "l"(a), "l"(b));
    return r;
}

__device__ __forceinline__ float hsum2(unsigned long long a) {
    float lo, hi;
    asm("mov.b64 {%0, %1}, %2;" : "=f"(lo), "=f"(hi) : "l"(a));
    return lo + hi;
}

__device__ __forceinline__ float tanh_fast(float x) {
    float y;
    asm("tanh.approx.f32 %0, %1;" : "=f"(y) : "f"(x));
    return y;
}

__device__ __forceinline__ void cp_async16(void* smem_dst, const void* gmem_src) {
    unsigned s = (unsigned)__cvta_generic_to_shared(smem_dst);
    asm volatile("cp.async.cg.shared.global [%0], [%1], 16;"
                 :: "r"(s), "l"(gmem_src) : "memory");
}

__device__ __forceinline__ int ld_acq(const int* p) {
    int v;
    asm volatile("ld.acquire.gpu.b32 %0, [%1];" : "=r"(v) : "l"(p) : "memory");
    return v;
}

__device__ __forceinline__ void st_rel(int* p, int v) {
    asm volatile("st.release.gpu.b32 [%0], %1;" :: "l"(p), "r"(v) : "memory");
}

// ---------------------------------------------------------------------------
// Probe resets dtype (reads 128 KB — in-bounds for every candidate layout)
// and clear the per-timestep ready flags for this replay.
// ---------------------------------------------------------------------------
__global__ void probe_clear_kernel(const unsigned int* __restrict__ r) {
    for (int i = threadIdx.x; i < TT; i += blockDim.x) g_ready[i] = 0;
    __shared__ int s_not01, s_notf;
    if (threadIdx.x == 0) { s_not01 = 0; s_notf = 0; }
    __syncthreads();
    int not01 = 0, notf = 0;
    for (int i = threadIdx.x; i < 32768; i += blockDim.x) {
        unsigned v = r[i];
        if (v != 0u && v != 1u) not01 = 1;
        if (v != 0u && v != 0x3F800000u) notf = 1;
    }
    if (not01) atomicOr(&s_not01, 1);
    if (notf)  atomicOr(&s_notf, 1);
    __syncthreads();
    if (threadIdx.x == 0)
        g_reset_mode = (!s_not01) ? 0 : ((!s_notf) ? 1 : 2);
}

// ---------------------------------------------------------------------------
// GEMM role: blocks BB..grid-1. Block gb owns timesteps t = gb + k*ngemm.
// ---------------------------------------------------------------------------
__device__ __forceinline__ void gemm_role(const float* __restrict__ x,
                                          const float* __restrict__ Wi,
                                          const float* __restrict__ bi,
                                          int gb, int ngemm) {
    __shared__ __align__(16) float xs[2][DD];
    const int j = threadIdx.x;

    unsigned long long w2[64];
#pragma unroll
    for (int k = 0; k < 64; k++)
        w2[k] = pack2(Wi[(2 * k) * D3 + j], Wi[(2 * k + 1) * D3 + j]);
    const float bj = bi[j];

    for (int t = gb; t < TT; t += ngemm) {
        const int r0 = t * BB;
        for (int rp = 0; rp < BB; rp += 2) {
            const int r = r0 + rp;
            if (j < 256)
                xs[j >> 7][j & 127] = x[(size_t)(r + (j >> 7)) * DD + (j & 127)];
            __syncthreads();

            unsigned long long a00 = 0ull, a01 = 0ull, a10 = 0ull, a11 = 0ull;
            const ulonglong2* x0 = (const ulonglong2*)xs[0];
            const ulonglong2* x1 = (const ulonglong2*)xs[1];
#pragma unroll
            for (int k = 0; k < 32; k++) {
                ulonglong2 v0 = x0[k];
                ulonglong2 v1 = x1[k];
                fma2(a00, w2[2 * k],     v0.x);
                fma2(a01, w2[2 * k + 1], v0.y);
                fma2(a10, w2[2 * k],     v1.x);
                fma2(a11, w2[2 * k + 1], v1.y);
            }
            g_xi[(size_t)r * D3 + j]       = bj + hsum2(add2(a00, a01));
            g_xi[(size_t)(r + 1) * D3 + j] = bj + hsum2(add2(a10, a11));
            __syncthreads();
        }
        // Publish timestep t: fence all threads' STGs, then release store.
        __threadfence();
        __syncthreads();
        if (j == 0) st_rel(&g_ready[t], 1);
    }
}

// ---------------------------------------------------------------------------
// Scan role: blocks 0..31, one per batch element. Warp-specialized step:
//   dot phase (all 12 warps): hh[j] = <Wh[:,j], h[p]>  (unconditional; gate
//     warps additionally preload xi/reset for this step into registers)
//   B1
//   window:  warps 0-3  -> gate math via MUFU.TANH (+reset selects), write h
//            warps 4-7  -> store ys for step t-1 from stable h[p]
//            warps 8-10 -> frontier check + cp.async refill of slot st
//   B2
// ---------------------------------------------------------------------------
__device__ __forceinline__ void scan_role(const void* __restrict__ resets,
                                          const float* __restrict__ Wh,
                                          const float* __restrict__ bhn,
                                          float* __restrict__ ys, int b) {
    __shared__ __align__(16) float h[2][DD];
    __shared__ float hh[D3];
    __shared__ __align__(16) float xstage[NSTAGE][D3];
    __shared__ unsigned char srst[TT];

    const int j = threadIdx.x;
    const int d = j & 127;
    const int mode = g_reset_mode;

    const bool is_gate = (j < 128);
    const bool is_ys   = (j >= 128 && j < 256);
    const bool is_refl = (j >= 256 && j < 352);
    const int  rl      = j - 256;  // refill lane 0..95

    unsigned long long w2[64];
#pragma unroll
    for (int k = 0; k < 64; k++)
        w2[k] = pack2(Wh[(2 * k) * D3 + j], Wh[(2 * k + 1) * D3 + j]);
    const float bn = is_gate ? bhn[d] : 0.0f;

    if (j < DD) h[0][j] = 0.0f;

    for (int t = j; t < TT; t += 384)
        srst[t] = (unsigned char)read_reset(resets, t * BB + b, mode);

    // Prime the ring (refill warps own all cp.async group state).
    if (is_refl) {
        for (int s = 0; s < NSTAGE; s++) {
            while (ld_acq(&g_ready[s]) == 0) __nanosleep(64);
            cp_async16(&xstage[s][rl * 4],
                       g_xi + ((size_t)s * BB + b) * D3 + rl * 4);
            asm volatile("cp.async.commit_group;" ::: "memory");
        }
        // Slot 0 must be complete before the t=0 gate preload reads it.
        asm volatile("cp.async.wait_group %0;" :: "n"(NSTAGE - 1) : "memory");
    }
    __syncthreads();

    // Running pointers. yp: next output row to write (row t-1 at iter t).
    float* yp = is_ys ? (ys + (size_t)b * DD + (j - 128)) : ys;
    const float* rp = g_xi + ((size_t)NSTAGE * BB + b) * D3 + rl * 4;

    int F = NSTAGE;  // uniform across refill warps
    int p = 0;
    for (int t = 0; t < TT; t++) {
        const int st = t & (NSTAGE - 1);

        // Gate warps preload this step's xi + reset flag (registers), so the
        // refill warps may overwrite slot st during the window.
        float xr = 0.0f, xz = 0.0f, xn = 0.0f;
        int rst = 0;
        if (is_gate) {
            const float* xi_s = xstage[st];
            xr = xi_s[d];
            xz = xi_s[128 + d];
            xn = xi_s[256 + d];
            rst = srst[t];
        }

        // Unconditional dot: hh[j] = <Wh[:,j], h[p]>.
        unsigned long long a0 = 0ull, a1 = 0ull, a2 = 0ull, a3 = 0ull;
        const ulonglong2* h2 = (const ulonglong2*)h[p];
#pragma unroll
        for (int k = 0; k < 16; k++) {
            ulonglong2 va = h2[2 * k];
            ulonglong2 vb = h2[2 * k + 1];
            fma2(a0, w2[4 * k + 0], va.x);
            fma2(a1, w2[4 * k + 1], va.y);
            fma2(a2, w2[4 * k + 2], vb.x);
            fma2(a3, w2[4 * k + 3], vb.y);
        }
        hh[j] = hsum2(add2(add2(a0, a1), add2(a2, a3)));
        __syncthreads();  // B1: hh published; slot-st reads done.

        if (is_gate) {
            float hr = rst ? 0.0f : hh[d];
            float hz = rst ? 0.0f : hh[128 + d];
            float sn = (rst ? 0.0f : hh[256 + d]) + bn;  // hn + bhn
            // sigmoid(x) = 0.5 + 0.5*tanh(x/2); tanh via MUFU.TANH.
            float rg = 0.5f + 0.5f * tanh_fast(0.5f * (xr + hr));
            float zg = 0.5f + 0.5f * tanh_fast(0.5f * (xz + hz));
            float ng = tanh_fast(xn + rg * sn);
            float hp = rst ? 0.0f : h[p][d];
            h[p ^ 1][d] = ng + zg * (hp - ng);   // (1-z)*n + z*h
        } else if (is_ys) {
            if (t > 0) {                      // h[p] == output of step t-1
                *yp = h[p][j - 128];          // row t-1
                yp += BB * DD;                // advance only when written
            }
        } else if (is_refl) {
            const int need = t + NSTAGE;
            if (need < TT) {
                if (need >= F) {
                    int probe_t = need + 256;
                    if (probe_t > TT - 1) probe_t = TT - 1;
                    if (ld_acq(&g_ready[probe_t])) {
                        F = probe_t + 1;
                    } else {
                        while (ld_acq(&g_ready[need]) == 0) __nanosleep(64);
                        F = need + 1;
                    }
                }
                cp_async16(&xstage[st][rl * 4], rp);
            }
            rp += (size_t)BB * D3;
            asm volatile("cp.async.commit_group;" ::: "memory");
            // Next step's slot (oldest pending group) must be complete
            // before this thread's B2 arrival publishes it.
            asm volatile("cp.async.wait_group %0;" :: "n"(NSTAGE - 1) : "memory");
        }
        __syncthreads();  // B2: new h (+ next slot) published.

        p ^= 1;
    }

    if (is_ys) *yp = h[p][j - 128];  // row TT-1
}

// ---------------------------------------------------------------------------
// Fused kernel: blocks 0..31 scan, blocks 32.. run the producer GEMM.
// >=128 regs/thread -> 1 CTA/SM; grid == #SMs => all CTAs resident in wave 1,
// so the producer/consumer handshake cannot deadlock.
// ---------------------------------------------------------------------------
__global__ __launch_bounds__(384, 1)
void fused_kernel(const float* __restrict__ x,
                  const void* __restrict__ resets,
                  const float* __restrict__ Wi,
                  const float* __restrict__ bi,
                  const float* __restrict__ Wh,
                  const float* __restrict__ bhn,
                  float* __restrict__ ys,
                  int ngemm) {
    if (blockIdx.x < BB)
        scan_role(resets, Wh, bhn, ys, blockIdx.x);
    else
        gemm_role(x, Wi, bi, blockIdx.x - BB, ngemm);
}

// ---------------------------------------------------------------------------
extern "C" void kernel_launch(void* const* d_in, const int* in_sizes, int n_in,
                              void* d_out, int out_size) {
    const float* x      = (const float*)d_in[0];
    const void*  resets = d_in[1];
    const float* Wi     = (const float*)d_in[2];
    const float* bi     = (const float*)d_in[3];
    const float* Wh     = (const float*)d_in[4];
    const float* bhn    = (const float*)d_in[5];
    float* ys = (float*)d_out;

    int dev = 0, nsm = 148;
    cudaGetDevice(&dev);
    cudaDeviceGetAttribute(&nsm, cudaDevAttrMultiProcessorCount, dev);
    if (nsm < BB + 1) nsm = BB + 1;

    probe_clear_kernel<<<1, 256>>>((const unsigned int*)resets);
    fused_kernel<<<nsm, 384>>>(x, resets, Wi, bi, Wh, bhn, ys, nsm - BB);
}